// round 16
// baseline (speedup 1.0000x reference)
#include <cuda_runtime.h>

#define T_LEN 2048
#define BATCH 64
#define XDIM  64
#define HID   256
#define KH    256            // recurrent K (x part precomputed)
#define KW    16             // K per warp (GEMV granularity)

#define NCTA  128            // 2 batch-halves x 64 column-slices
#define NTHR  512            // 16 warps, warp w = k-slice [16w,16w+16)

// Static device scratch (no cudaMalloc anywhere)
__device__ float4 g_xz[(size_t)T_LEN * HID * BATCH];   // [t][col][b] pre-activations
__device__ __align__(16) float2 g_h2[2][KH][BATCH];    // tagged h: {h, tag}
__device__ unsigned g_epoch;                           // replay epoch counter

// ---------------- packed f32x2 helpers ----------------
__device__ __forceinline__ unsigned long long fma2_(unsigned long long a,
                                                    unsigned long long b,
                                                    unsigned long long c) {
    unsigned long long d;
    asm("fma.rn.f32x2 %0, %1, %2, %3;" : "=l"(d) : "l"(a), "l"(b), "l"(c));
    return d;
}
__device__ __forceinline__ unsigned long long add2_(unsigned long long a,
                                                    unsigned long long b) {
    unsigned long long d;
    asm("add.rn.f32x2 %0, %1, %2;" : "=l"(d) : "l"(a), "l"(b));
    return d;
}
__device__ __forceinline__ unsigned long long dup2_(float x) {
    unsigned long long d;
    asm("mov.b64 %0, {%1, %1};" : "=l"(d) : "r"(__float_as_uint(x)));
    return d;
}
__device__ __forceinline__ unsigned long long pack2_(float lo, float hi) {
    unsigned long long d;
    asm("mov.b64 %0, {%1, %2};" : "=l"(d) : "r"(__float_as_uint(lo)), "r"(__float_as_uint(hi)));
    return d;
}
__device__ __forceinline__ void unpack2_(unsigned long long v, float& lo, float& hi) {
    unsigned a, b;
    asm("mov.b64 {%0, %1}, %2;" : "=r"(a), "=r"(b) : "l"(v));
    lo = __uint_as_float(a); hi = __uint_as_float(b);
}
// HW tanh (MUFU.TANH, sm_75+)
__device__ __forceinline__ float tanh_hw_(float x) {
    float y;
    asm("tanh.approx.f32 %0, %1;" : "=f"(y) : "f"(x));
    return y;
}
__device__ __forceinline__ float sigmoid_hw_(float x) {   // 0.5*tanh(x/2)+0.5
    return __fmaf_rn(0.5f, tanh_hw_(0.5f * x), 0.5f);
}

// Volatile tagged 8B load/store (single transaction -> no tearing)
__device__ __forceinline__ float2 vld2_(const float2* p) {
    float2 v;
    asm volatile("ld.volatile.global.v2.f32 {%0,%1}, [%2];"
                 : "=f"(v.x), "=f"(v.y) : "l"(p));
    return v;
}
__device__ __forceinline__ void vst2_(float2* p, float h, unsigned tag) {
    asm volatile("st.volatile.global.v2.f32 [%0], {%1,%2};"
                 :: "l"(p), "f"(h), "f"(__uint_as_float(tag)) : "memory");
}
// smem release/acquire flag ops (cta scope)
__device__ __forceinline__ void flag_release_(unsigned addr, unsigned val) {
    asm volatile("st.release.cta.shared.u32 [%0], %1;"
                 :: "r"(addr), "r"(val) : "memory");
}
__device__ __forceinline__ unsigned flag_acquire_(unsigned addr) {
    unsigned v;
    asm volatile("ld.acquire.cta.shared.u32 %0, [%1];"
                 : "=r"(v) : "r"(addr) : "memory");
    return v;
}

// ---------------------------------------------------------------------------
// Pre-kernel: g_xz[t][col][b] = bias + x[b,t,:] . w_ih[4 gate rows of col, :]
// Retiled (R14, proven): thread = 2 batches (b0, b0+32) x 8 cols.
// ---------------------------------------------------------------------------
#define PG_COLS 64
__global__ void __launch_bounds__(256) xz_gemm_kernel(
    const float* __restrict__ x, const float* __restrict__ w_ih,
    const float* __restrict__ bias)
{
    extern __shared__ float ps[];
    float (*xs)[65] = (float(*)[65])ps;          // [b][k], padded (16.6 KB)
    float* ws = ps + 64 * 65;                    // [c64][k64][q4]   (64 KB)

    const int t       = blockIdx.y;
    const int colbase = blockIdx.x * PG_COLS;
    const int tid     = threadIdx.x;

    for (int i = tid; i < 64 * 16; i += 256) {
        int b = i >> 4, k4 = i & 15;
        float4 v = *(const float4*)(x + (size_t)b * (T_LEN * XDIM) + (size_t)t * XDIM + 4 * k4);
        xs[b][4 * k4 + 0] = v.x; xs[b][4 * k4 + 1] = v.y;
        xs[b][4 * k4 + 2] = v.z; xs[b][4 * k4 + 3] = v.w;
    }
    for (int i = tid; i < PG_COLS * 64 * 4; i += 256) {
        int q = i & 3, k = (i >> 2) & 63, c = i >> 8;
        ws[i] = w_ih[(q * HID + colbase + c) * XDIM + k];
    }
    __syncthreads();

    const int b0 = tid & 31;                     // batches b0 and b0+32
    const int cg = tid >> 5;                     // 0..7 -> cols cg*8..cg*8+7
    unsigned long long a01[8][2], a23[8][2];
    #pragma unroll
    for (int c8 = 0; c8 < 8; ++c8) {
        int col = colbase + cg * 8 + c8;
        unsigned long long b01 = pack2_(bias[0 * HID + col], bias[1 * HID + col]);
        unsigned long long b23 = pack2_(bias[2 * HID + col], bias[3 * HID + col]);
        a01[c8][0] = b01; a01[c8][1] = b01;
        a23[c8][0] = b23; a23[c8][1] = b23;
    }
    #pragma unroll 2
    for (int k = 0; k < 64; ++k) {
        unsigned long long xv0 = dup2_(xs[b0][k]);
        unsigned long long xv1 = dup2_(xs[b0 + 32][k]);
        #pragma unroll
        for (int c8 = 0; c8 < 8; ++c8) {
            ulonglong2 w = *(ulonglong2*)&ws[((cg * 8 + c8) * 64 + k) * 4];
            a01[c8][0] = fma2_(w.x, xv0, a01[c8][0]);
            a23[c8][0] = fma2_(w.y, xv0, a23[c8][0]);
            a01[c8][1] = fma2_(w.x, xv1, a01[c8][1]);
            a23[c8][1] = fma2_(w.y, xv1, a23[c8][1]);
        }
    }
    #pragma unroll
    for (int c8 = 0; c8 < 8; ++c8) {
        int col = colbase + cg * 8 + c8;
        float4 o0, o1;
        unpack2_(a01[c8][0], o0.x, o0.y);
        unpack2_(a23[c8][0], o0.z, o0.w);
        unpack2_(a01[c8][1], o1.x, o1.y);
        unpack2_(a23[c8][1], o1.z, o1.w);
        g_xz[((size_t)t * HID + col) * BATCH + b0]      = o0;
        g_xz[((size_t)t * HID + col) * BATCH + b0 + 32] = o1;
    }
}

// ---------------------------------------------------------------------------
// Persistent LSTM, tagged dataflow, FULLY DECOUPLED warps (no in-loop
// __syncthreads): per-warp monotonic smem flags with release/acquire.
//   Warp w (k-slice [16w,16w+16)): detect tags -> GEMV -> STS partials ->
//   __syncwarp -> lane0 st.release flags[w]=t+1 -> next step immediately.
//   Owner warps 0-3 (col 4s+cw): also poll all 16 flags (ld.acquire,
//   lane-parallel) -> reduce -> pointwise -> publish h(t+1).
//   p1 WAR at distance 2 WITHOUT a barrier: warp W's p1(t+2) write requires
//   detecting h(t+2); h(t+2) of ANY col requires (via that col's CTA, whose
//   16 warps' slices span ALL 256 cols) h(t+1) of ALL cols, including this
//   CTA's -- published only after our owners read p1(t). Two-hop chain ==
//   distance-2 ordering. h exchange WAR: same tag-chain argument as before.
// ---------------------------------------------------------------------------
__global__ void __launch_bounds__(NTHR, 1) lstm_kernel(
    const float* __restrict__ w_hh, float* __restrict__ out)
{
    extern __shared__ __align__(16) float smem[];
    float* wsm = smem;                                     // [256k][4c][4g] 16KB
    ulonglong2* part1 = (ulonglong2*)(smem + 4 * KH * 4);  // [2][16w][4c][32l] 64KB
    __shared__ unsigned flags[16];                         // monotonic step counters
    __shared__ unsigned sh_epoch;

    const int tid   = threadIdx.x;
    const int warp  = tid >> 5;
    const int lane  = tid & 31;
    const int cw    = warp & 3;           // col duty (owners: warp==cw)
    const int s     = blockIdx.x & 63;
    const int beta  = blockIdx.x >> 6;
    const int col   = 4 * s + cw;
    const int b     = 32 * beta + lane;
    const bool owner = (warp < 4);

    if (tid == 0) sh_epoch = atomicAdd(&g_epoch, 1u) >> 7;   // /NCTA -> replay id
    if (tid < 16) flags[tid] = 0u;

    // Weights: wsm[((k*4 + c)*4) + q] = w_hh[q*HID + 4s+c][k], gates i,f,g,o
    for (int idx = tid; idx < 4 * KH * 4; idx += NTHR) {
        int q = idx & 3, c = (idx >> 2) & 3, k = idx >> 4;
        wsm[idx] = w_hh[(q * HID + 4 * s + c) * HID + k];
    }
    __syncthreads();                       // weights + flags visible CTA-wide
    const unsigned epoch = sh_epoch;
    const unsigned tag0  = epoch * (unsigned)(T_LEN + 1) + 1u;  // tag(h_t)=tag0+t

    const unsigned myflag_addr  = (unsigned)__cvta_generic_to_shared(&flags[warp]);
    const unsigned pollflag_addr = (unsigned)__cvta_generic_to_shared(&flags[lane & 15]);

    float c_reg = 0.0f;
    float4 xz = make_float4(0.f, 0.f, 0.f, 0.f);
    float2* gh2 = &g_h2[0][0][0];
    if (owner) {
        vst2_(gh2 + (size_t)col * BATCH + b, 0.0f, tag0);     // h(0)=0, slot 0
        xz = __ldcg(&g_xz[(size_t)col * BATCH + b]);          // xz(t=0)
    }

    const size_t out_base = (size_t)b * (T_LEN * HID) + col;
    const ulonglong2* wk = (const ulonglong2*)wsm + warp * KW * 4;   // [k16][c4]
    const float2* src0 = gh2 + (size_t)(warp * KW) * BATCH + b;      // slot 0

    for (int t = 0; t < T_LEN; ++t) {
        const unsigned exp = tag0 + (unsigned)t;
        const int buf = t & 1;
        const float2* src = src0 + (size_t)buf * (KH * BATCH);
        ulonglong2* p1 = part1 + (size_t)buf * (16 * 4 * 32);

        // Fire all 16 tagged loads (MLP=16, coalesced per k) up front.
        float2 v[KW];
        #pragma unroll
        for (int i = 0; i < KW; ++i) v[i] = vld2_(src + i * BATCH);

        // FMA-on-arrival: consume in 4 groups of 4.
        unsigned long long a01[4] = {0ull, 0ull, 0ull, 0ull};
        unsigned long long a23[4] = {0ull, 0ull, 0ull, 0ull};
        #pragma unroll
        for (int g = 0; g < 4; ++g) {
            while (true) {
                bool ok = true;
                #pragma unroll
                for (int j = 0; j < 4; ++j)
                    ok &= (__float_as_uint(v[g * 4 + j].y) == exp);
                if (__all_sync(0xffffffffu, ok)) break;
                #pragma unroll
                for (int j = 0; j < 4; ++j)
                    if (__float_as_uint(v[g * 4 + j].y) != exp)
                        v[g * 4 + j] = vld2_(src + (g * 4 + j) * BATCH);
            }
            #pragma unroll
            for (int j = 0; j < 4; ++j) {
                int k = g * 4 + j;
                unsigned long long hv2 = dup2_(v[k].x);
                #pragma unroll
                for (int c = 0; c < 4; ++c) {
                    ulonglong2 w2 = wk[k * 4 + c];
                    a01[c] = fma2_(w2.x, hv2, a01[c]);
                    a23[c] = fma2_(w2.y, hv2, a23[c]);
                }
            }
        }
        #pragma unroll
        for (int c = 0; c < 4; ++c) {
            ulonglong2 pv; pv.x = a01[c]; pv.y = a23[c];
            p1[(warp * 4 + c) * 32 + lane] = pv;
        }
        __syncwarp();                                   // lanes' STS ordered
        if (lane == 0) flag_release_(myflag_addr, (unsigned)(t + 1));

        if (owner) {   // poll all 16 flags (lane-parallel acquire), reduce
            while (true) {
                bool ok = true;
                if (lane < 16)
                    ok = ((int)(flag_acquire_(pollflag_addr) - (unsigned)(t + 1)) >= 0);
                if (__all_sync(0xffffffffu, ok)) break;
            }
            __syncwarp();             // propagate all acquires to all lanes

            ulonglong2 r[16];
            #pragma unroll
            for (int w = 0; w < 16; ++w)
                r[w] = p1[(w * 4 + cw) * 32 + lane];
            #pragma unroll
            for (int d = 8; d >= 1; d >>= 1)
                #pragma unroll
                for (int w = 0; w < d; ++w) {                // balanced tree
                    r[w].x = add2_(r[w].x, r[w + d].x);
                    r[w].y = add2_(r[w].y, r[w + d].y);
                }
            unsigned long long acc01 = add2_(r[0].x, pack2_(xz.x, xz.y));
            unsigned long long acc23 = add2_(r[0].y, pack2_(xz.z, xz.w));
            float a0, a1, a2, a3;
            unpack2_(acc01, a0, a1);
            unpack2_(acc23, a2, a3);

            const float ig = sigmoid_hw_(a0);
            const float fg = sigmoid_hw_(a1);
            const float gg = tanh_hw_(a2);
            const float og = sigmoid_hw_(a3);
            c_reg = fmaf(fg, c_reg, ig * gg);
            const float h = og * tanh_hw_(c_reg);

            // Publish FIRST (consumers spin on this), then sideband stores.
            vst2_(gh2 + (size_t)((t + 1) & 1) * (KH * BATCH)
                      + (size_t)col * BATCH + b, h, exp + 1u);
            out[out_base + (size_t)t * HID] = h;
            if (t + 1 < T_LEN)
                xz = __ldcg(&g_xz[((size_t)(t + 1) * HID + col) * BATCH + b]);
        }
        // Non-owner warps are already free-running into step t+1.
    }
}

// ---------------------------------------------------------------------------
extern "C" void kernel_launch(void* const* d_in, const int* in_sizes, int n_in,
                              void* d_out, int out_size) {
    (void)in_sizes; (void)n_in; (void)out_size;
    const float* x    = (const float*)d_in[0];
    const float* w_ih = (const float*)d_in[1];
    const float* w_hh = (const float*)d_in[2];
    const float* bias = (const float*)d_in[3];
    float* out = (float*)d_out;

    const int pg_smem = (64 * 65 + PG_COLS * 64 * 4) * (int)sizeof(float); // ~82 KB
    cudaFuncSetAttribute(xz_gemm_kernel,
                         cudaFuncAttributeMaxDynamicSharedMemorySize, pg_smem);
    const int ls_smem = 4 * KH * 4 * (int)sizeof(float)
                        + 2 * 16 * 4 * 32 * (int)sizeof(ulonglong2);  // 16+64 KB
    cudaFuncSetAttribute(lstm_kernel,
                         cudaFuncAttributeMaxDynamicSharedMemorySize, ls_smem);

    dim3 pg_grid(HID / PG_COLS, T_LEN);
    xz_gemm_kernel<<<pg_grid, 256, pg_smem>>>(x, w_ih, bias);
    lstm_kernel<<<NCTA, NTHR, ls_smem>>>(w_hh, out);
}